// round 16
// baseline (speedup 1.0000x reference)
#include <cuda_runtime.h>
#include <cuda_bf16.h>
#include <cuda_fp16.h>
#include <cstdint>

#define N_NODES 100000
#define N_EDGES 1600000
#define D 128
#define SCAN_BS 512
#define NB ((N_NODES + SCAN_BS - 1) / SCAN_BS)   // 196
#define GEMM_TILE_M 64
#define N_TILES ((N_NODES + GEMM_TILE_M - 1) / GEMM_TILE_M)   // 1563
#define PITCH_B 272
#define GEMM_CTAS 148

// ---------------- scratch ----------------------------------------------------
__device__ __half g_yh[N_NODES * D];
__device__ float g_dinv[N_NODES];
__device__ int   g_cnt[N_NODES];
__device__ int   g_rank[N_EDGES];
__device__ int   g_rowptr[N_NODES];
__device__ int   g_src[N_EDGES];
__device__ int   g_bsum[NB];
__device__ __align__(16) __nv_bfloat16 g_Ahi[N_NODES * D];
__device__ __align__(16) __nv_bfloat16 g_Alo[N_NODES * D];
__device__ __align__(16) __nv_bfloat16 g_Xhi[N_NODES * D];
__device__ __align__(16) __nv_bfloat16 g_Xlo[N_NODES * D];
__device__ __align__(16) unsigned char g_Bhi[65536];
__device__ __align__(16) unsigned char g_Blo[65536];
__device__ unsigned g_barcnt = 0;
__device__ unsigned g_bargen = 0;

__device__ __forceinline__ void grid_barrier() {
    __syncthreads();
    if (threadIdx.x == 0) {
        unsigned gen;
        asm volatile("ld.acquire.gpu.u32 %0, [%1];" : "=r"(gen) : "l"(&g_bargen));
        __threadfence();
        unsigned ticket = atomicAdd(&g_barcnt, 1);
        if (ticket == gridDim.x - 1) {
            g_barcnt = 0;
            __threadfence();
            atomicAdd(&g_bargen, 1);
        } else {
            unsigned cur;
            do {
                asm volatile("ld.acquire.gpu.u32 %0, [%1];" : "=r"(cur) : "l"(&g_bargen));
            } while (cur == gen);
        }
    }
    __syncthreads();
}

__device__ __forceinline__ void split2x2(float4 v, uint2& hp, uint2& lp) {
    __nv_bfloat16 h0 = __float2bfloat16_rn(v.x);
    __nv_bfloat16 h1 = __float2bfloat16_rn(v.y);
    __nv_bfloat16 h2 = __float2bfloat16_rn(v.z);
    __nv_bfloat16 h3 = __float2bfloat16_rn(v.w);
    __nv_bfloat16 l0 = __float2bfloat16_rn(v.x - __bfloat162float(h0));
    __nv_bfloat16 l1 = __float2bfloat16_rn(v.y - __bfloat162float(h1));
    __nv_bfloat16 l2 = __float2bfloat16_rn(v.z - __bfloat162float(h2));
    __nv_bfloat16 l3 = __float2bfloat16_rn(v.w - __bfloat162float(h3));
    hp.x = (uint32_t)__bfloat16_as_ushort(h0) | ((uint32_t)__bfloat16_as_ushort(h1) << 16);
    hp.y = (uint32_t)__bfloat16_as_ushort(h2) | ((uint32_t)__bfloat16_as_ushort(h3) << 16);
    lp.x = (uint32_t)__bfloat16_as_ushort(l0) | ((uint32_t)__bfloat16_as_ushort(l1) << 16);
    lp.y = (uint32_t)__bfloat16_as_ushort(l2) | ((uint32_t)__bfloat16_as_ushort(l3) << 16);
}

// ---------------- launch 0: zero + wconv -> barrier -> count ----------------
__global__ __launch_bounds__(SCAN_BS, 2)
void k_count(const int* __restrict__ col,
             const float* __restrict__ Wconv, const float* __restrict__ Wproj) {
    int tid0 = blockIdx.x * SCAN_BS + threadIdx.x;
    if (tid0 < N_NODES) g_cnt[tid0] = 0;
    if (tid0 < 128 * 128) {
        int t = tid0;
        int n = t >> 7;
        int p = t & 127;
        int k0 = 2 * p, k1 = k0 + 1;
        float v0 = (k0 < D) ? Wconv[k0 * D + n] : Wproj[(k0 - D) * D + n];
        float v1 = (k1 < D) ? Wconv[k1 * D + n] : Wproj[(k1 - D) * D + n];
        __nv_bfloat16 h0 = __float2bfloat16_rn(v0);
        __nv_bfloat16 h1 = __float2bfloat16_rn(v1);
        __nv_bfloat16 l0 = __float2bfloat16_rn(v0 - __bfloat162float(h0));
        __nv_bfloat16 l1 = __float2bfloat16_rn(v1 - __bfloat162float(h1));
        uint32_t hp = (uint32_t)__bfloat16_as_ushort(h0) | ((uint32_t)__bfloat16_as_ushort(h1) << 16);
        uint32_t lp = (uint32_t)__bfloat16_as_ushort(l0) | ((uint32_t)__bfloat16_as_ushort(l1) << 16);
        int half = k0 >> 7;
        int klocal = k0 & 127;
        uint32_t off = ((uint32_t)half * 16384 + n * 128 + klocal) * 2;
        *(uint32_t*)(g_Bhi + off) = hp;
        *(uint32_t*)(g_Blo + off) = lp;
    }
    grid_barrier();
    int nthreads = gridDim.x * SCAN_BS;
    for (int e = tid0; e < N_EDGES; e += nthreads)
        g_rank[e] = atomicAdd(&g_cnt[col[e]], 1);
}

// ---------------- launch 1: block sums -> barrier -> prefix + rowptr/dinv ---
__global__ __launch_bounds__(SCAN_BS, 2)
void k_scan() {
    __shared__ int s[SCAN_BS];
    __shared__ int s2[256];
    int t = threadIdx.x;
    int bid = blockIdx.x;
    int i = bid * SCAN_BS + t;
    int v = (i < N_NODES) ? g_cnt[i] : 0;
    s[t] = v;
    __syncthreads();
    for (int off = 1; off < SCAN_BS; off <<= 1) {
        int u = (t >= off) ? s[t - off] : 0;
        __syncthreads();
        s[t] += u;
        __syncthreads();
    }
    if (t == SCAN_BS - 1) g_bsum[bid] = s[t];
    int local_incl = s[t];
    grid_barrier();
    if (t < 256) s2[t] = (t < NB) ? g_bsum[t] : 0;
    __syncthreads();
    for (int off = 1; off < 256; off <<= 1) {
        int u = 0;
        if (t < 256 && t >= off) u = s2[t - off];
        __syncthreads();
        if (t < 256) s2[t] += u;
        __syncthreads();
    }
    int bpre = (bid > 0) ? s2[bid - 1] : 0;
    if (i < N_NODES) {
        g_rowptr[i] = local_incl - v + bpre;
        g_dinv[i] = rsqrtf((float)(v + 2));
    }
}

// ---------------- launch 2: prep (yh = dinv*x fp16) + fill ------------------
#define PREP_BLOCKS 12500
__global__ void k_prepfill(const float* __restrict__ x,
                           const int* __restrict__ rowv, const int* __restrict__ colv) {
    if (blockIdx.x < PREP_BLOCKS) {
        int i = blockIdx.x * 256 + threadIdx.x;
        if (i >= N_NODES * 32) return;
        int node = i >> 5;
        float dv = g_dinv[node];
        float4 v = ((const float4*)x)[i];
        __half2 a = __floats2half2_rn(dv * v.x, dv * v.y);
        __half2 b = __floats2half2_rn(dv * v.z, dv * v.w);
        uint2 u;
        u.x = *(uint32_t*)&a;
        u.y = *(uint32_t*)&b;
        ((uint2*)g_yh)[i] = u;
    } else {
        int e = (blockIdx.x - PREP_BLOCKS) * 256 + threadIdx.x;
        if (e >= N_EDGES) return;
        int pos = g_rowptr[colv[e]] + g_rank[e];
        g_src[pos] = rowv[e];
    }
}

// ---------------- launch 3 (PROFILED): gather agg + A/X split ---------------
__global__ void k_agg(const float* __restrict__ x) {
    int w = (blockIdx.x * blockDim.x + threadIdx.x) >> 5;
    int lane = threadIdx.x & 31;
    if (w >= N_NODES) return;
    const uint2* yh2 = (const uint2*)g_yh;

    int start = g_rowptr[w];
    int cn = g_cnt[w];

    float ax = 0.f, ay = 0.f, az = 0.f, aw = 0.f;

    for (int base = 0; base < cn; base += 32) {
        int idx = 0;
        if (base + lane < cn) idx = g_src[start + base + lane];
        int m = min(32, cn - base);
        int j = 0;
        for (; j + 8 <= m; j += 8) {
            uint2 u[8];
#pragma unroll
            for (int q = 0; q < 8; q++) {
                int sv = __shfl_sync(0xffffffffu, idx, j + q);
                u[q] = yh2[sv * 32 + lane];
            }
            __half2 px0 = __hadd2(*(__half2*)&u[0].x, *(__half2*)&u[1].x);
            __half2 px1 = __hadd2(*(__half2*)&u[2].x, *(__half2*)&u[3].x);
            __half2 px2 = __hadd2(*(__half2*)&u[4].x, *(__half2*)&u[5].x);
            __half2 px3 = __hadd2(*(__half2*)&u[6].x, *(__half2*)&u[7].x);
            __half2 py0 = __hadd2(*(__half2*)&u[0].y, *(__half2*)&u[1].y);
            __half2 py1 = __hadd2(*(__half2*)&u[2].y, *(__half2*)&u[3].y);
            __half2 py2 = __hadd2(*(__half2*)&u[4].y, *(__half2*)&u[5].y);
            __half2 py3 = __hadd2(*(__half2*)&u[6].y, *(__half2*)&u[7].y);
            __half2 qx0 = __hadd2(px0, px1);
            __half2 qx1 = __hadd2(px2, px3);
            __half2 qy0 = __hadd2(py0, py1);
            __half2 qy1 = __hadd2(py2, py3);
            float2 fx0 = __half22float2(qx0);
            float2 fx1 = __half22float2(qx1);
            float2 fy0 = __half22float2(qy0);
            float2 fy1 = __half22float2(qy1);
            ax += fx0.x + fx1.x;
            ay += fx0.y + fx1.y;
            az += fy0.x + fy1.x;
            aw += fy0.y + fy1.y;
        }
        for (; j < m; j++) {
            int sv = __shfl_sync(0xffffffffu, idx, j);
            uint2 u0 = yh2[sv * 32 + lane];
            float2 a = __half22float2(*(__half2*)&u0.x);
            float2 b = __half22float2(*(__half2*)&u0.y);
            ax += a.x; ay += a.y; az += b.x; aw += b.y;
        }
    }

    float dc = g_dinv[w];
    float4 xv = ((const float4*)x)[w * 32 + lane];
    float td = 2.f * dc;
    float4 r;
    r.x = dc * (ax + td * xv.x);
    r.y = dc * (ay + td * xv.y);
    r.z = dc * (az + td * xv.z);
    r.w = dc * (aw + td * xv.w);

    uint2 hp, lp;
    split2x2(r, hp, lp);
    ((uint2*)g_Ahi)[w * 32 + lane] = hp;
    ((uint2*)g_Alo)[w * 32 + lane] = lp;
    split2x2(xv, hp, lp);
    ((uint2*)g_Xhi)[w * 32 + lane] = hp;
    ((uint2*)g_Xlo)[w * 32 + lane] = lp;
}

// ---------------- launch 4: persistent resident-B split-bf16 mma GEMM -------
// smem: A 4 images x 17408 @ 0; B 4 images x 34816 @ 69632; misc @ 208896
#define SM_A 0
#define SM_B 69632
#define SM_MISC 208896
#define SM_TOTAL 210432

__device__ __forceinline__ uint32_t s2u(const void* p) {
    uint32_t a;
    asm("{ .reg .u64 t; cvta.to.shared.u64 t, %1; cvt.u32.u64 %0, t; }" : "=r"(a) : "l"(p));
    return a;
}
__device__ __forceinline__ void ldsm4(uint32_t* r, uint32_t addr) {
    asm volatile("ldmatrix.sync.aligned.m8n8.x4.shared.b16 {%0,%1,%2,%3}, [%4];"
                 : "=r"(r[0]), "=r"(r[1]), "=r"(r[2]), "=r"(r[3]) : "r"(addr));
}
__device__ __forceinline__ void mma16816(float* c, const uint32_t* a, uint32_t b0, uint32_t b1) {
    asm volatile(
        "mma.sync.aligned.m16n8k16.row.col.f32.bf16.bf16.f32 "
        "{%0,%1,%2,%3}, {%4,%5,%6,%7}, {%8,%9}, {%0,%1,%2,%3};"
        : "+f"(c[0]), "+f"(c[1]), "+f"(c[2]), "+f"(c[3])
        : "r"(a[0]), "r"(a[1]), "r"(a[2]), "r"(a[3]), "r"(b0), "r"(b1));
}

__global__ __launch_bounds__(512, 1)
void k_gemm(const float* __restrict__ bconv, const float* __restrict__ bproj,
            const float* __restrict__ Wout,  const float* __restrict__ bout,
            float* __restrict__ out) {
    extern __shared__ char sm[];
    uint32_t sb = s2u(sm);
    int tid = threadIdx.x;
    int wid = tid >> 5;
    int lane = tid & 31;

    float* sB = (float*)(sm + SM_MISC);
    float* sO = (float*)(sm + SM_MISC + 512);
    float* sRes = (float*)(sm + SM_MISC + 1024);

    if (tid < D) {
        sB[tid] = bconv[tid] + bproj[tid];
        sO[tid] = Wout[tid];
    }
    float bo = bout[0];

    // ---- load B once: 4 images (hi_h0, lo_h0, hi_h1, lo_h1), padded rows ----
#pragma unroll
    for (int p = 0; p < 16; p++) {
        int i = p * 512 + tid;          // 8192 uint4
        int img = i >> 11;              // 0..3
        int j = i & 2047;
        int r = j >> 4;
        int u = j & 15;
        const unsigned char* src = ((img & 1) ? g_Blo : g_Bhi) + (img >> 1) * 32768 + r * 256 + u * 16;
        unsigned char* dst = (unsigned char*)sm + SM_B + img * 34816 + r * PITCH_B + u * 16;
        *(uint4*)dst = *(const uint4*)src;
    }

    int warp_m = wid & 1;     // 2 row groups of 32
    int warp_n = wid >> 1;    // 8 col groups of 16

    int l8 = lane & 7;
    int sel = lane >> 3;
    const uint4 zero4 = make_uint4(0, 0, 0, 0);

    for (int tile = blockIdx.x; tile < N_TILES; tile += gridDim.x) {
        int mBase = tile * GEMM_TILE_M;
        __syncthreads();   // prior tile fully consumed (ldsm + out-write done); B-load ordered on first iter

        if (tid < GEMM_TILE_M) sRes[tid] = 0.f;
        // ---- A copy: 4 images x 1024 uint4 (64 rows x 16) ----
#pragma unroll
        for (int p = 0; p < 8; p++) {
            int i = p * 512 + tid;      // 4096
            int img = i >> 10;          // 0..3: Ahi, Alo, Xhi, Xlo
            int j = i & 1023;
            int r = j >> 4;
            int u = j & 15;
            int node = mBase + r;
            uint4 v = zero4;
            if (node < N_NODES) {
                const uint4* srcA = (img == 0) ? (const uint4*)g_Ahi
                                  : (img == 1) ? (const uint4*)g_Alo
                                  : (img == 2) ? (const uint4*)g_Xhi
                                               : (const uint4*)g_Xlo;
                v = srcA[node * 16 + u];
            }
            *(uint4*)(sm + SM_A + img * 17408 + (uint32_t)r * PITCH_B + u * 16) = v;
        }
        __syncthreads();

        float acc[2][2][4];
#pragma unroll
        for (int mt = 0; mt < 2; mt++)
#pragma unroll
            for (int n8 = 0; n8 < 2; n8++)
#pragma unroll
                for (int j = 0; j < 4; j++) acc[mt][n8][j] = 0.f;

        // ---- mainloop: 2 halves x 8 ksteps, B resident ----
#pragma unroll
        for (int h = 0; h < 2; h++) {
            uint32_t aBaseHi = sb + SM_A + (h * 2) * 17408 + (warp_m * 32) * PITCH_B;
            uint32_t aBaseLo = aBaseHi + 17408;
            uint32_t bBaseHi = sb + SM_B + (h * 2) * 34816 + (warp_n * 16) * PITCH_B;
            uint32_t bBaseLo = bBaseHi + 34816;
#pragma unroll
            for (int ks = 0; ks < 8; ks++) {
                int kb = ks * 16;
                uint32_t ah[2][4], al[2][4];
#pragma unroll
                for (int mt = 0; mt < 2; mt++) {
                    int row = mt * 16 + l8 + (sel & 1) * 8;
                    int kk = kb + (sel >> 1) * 8;
                    uint32_t o = (uint32_t)row * PITCH_B + kk * 2;
                    ldsm4(ah[mt], aBaseHi + o);
                    ldsm4(al[mt], aBaseLo + o);
                }
                {
                    int row = (sel >> 1) * 8 + l8;
                    int kk = kb + (sel & 1) * 8;
                    uint32_t o = (uint32_t)row * PITCH_B + kk * 2;
                    uint32_t bh[4], bl[4];
                    ldsm4(bh, bBaseHi + o);
                    ldsm4(bl, bBaseLo + o);
#pragma unroll
                    for (int mt = 0; mt < 2; mt++) {
                        mma16816(acc[mt][0], ah[mt], bh[0], bh[1]);
                        mma16816(acc[mt][1], ah[mt], bh[2], bh[3]);
                        mma16816(acc[mt][0], ah[mt], bl[0], bl[1]);
                        mma16816(acc[mt][1], ah[mt], bl[2], bl[3]);
                        mma16816(acc[mt][0], al[mt], bh[0], bh[1]);
                        mma16816(acc[mt][1], al[mt], bh[2], bh[3]);
                    }
                }
            }
        }

        // ---- epilogue: relu + dot(W_out), smem atomic combine ----
#pragma unroll
        for (int mt = 0; mt < 2; mt++) {
            int r0 = warp_m * 32 + mt * 16 + (lane >> 2);
            float s0 = 0.f, s1 = 0.f;
#pragma unroll
            for (int n8 = 0; n8 < 2; n8++) {
                int c = warp_n * 16 + n8 * 8 + 2 * (lane & 3);
                s0 += fmaxf(acc[mt][n8][0] + sB[c], 0.f) * sO[c];
                s0 += fmaxf(acc[mt][n8][1] + sB[c + 1], 0.f) * sO[c + 1];
                s1 += fmaxf(acc[mt][n8][2] + sB[c], 0.f) * sO[c];
                s1 += fmaxf(acc[mt][n8][3] + sB[c + 1], 0.f) * sO[c + 1];
            }
            atomicAdd(&sRes[r0], s0);
            atomicAdd(&sRes[r0 + 8], s1);
        }
        __syncthreads();
        if (tid < GEMM_TILE_M) {
            int node = mBase + tid;
            if (node < N_NODES) out[node] = sRes[tid] + bo;
        }
    }
}

// ---------------- launch -----------------------------------------------------
extern "C" void kernel_launch(void* const* d_in, const int* in_sizes, int n_in,
                              void* d_out, int out_size) {
    const float* x      = (const float*)d_in[0];
    const int*   ei     = (const int*)d_in[1];
    const float* Wconv  = (const float*)d_in[2];
    const float* bconv  = (const float*)d_in[3];
    const float* Wproj  = (const float*)d_in[4];
    const float* bproj  = (const float*)d_in[5];
    const float* Wout   = (const float*)d_in[6];
    const float* bout   = (const float*)d_in[7];
    float* out = (float*)d_out;

    const int* rowv = ei;
    const int* colv = ei + N_EDGES;

    k_count<<<NB, SCAN_BS>>>(colv, Wconv, Wproj);              // 0
    k_scan<<<NB, SCAN_BS>>>();                                  // 1
    k_prepfill<<<PREP_BLOCKS + (N_EDGES + 255) / 256, 256>>>(x, rowv, colv);  // 2
    long long agg_threads = (long long)N_NODES * 32;
    k_agg<<<(unsigned)((agg_threads + 255) / 256), 256>>>(x);   // 3 (profiled)

    static bool attr_set = false;
    if (!attr_set) {
        cudaFuncSetAttribute(k_gemm, cudaFuncAttributeMaxDynamicSharedMemorySize, SM_TOTAL);
        attr_set = true;
    }
    k_gemm<<<GEMM_CTAS, 512, SM_TOTAL>>>(bconv, bproj, Wout, bout, out);      // 4
}

// round 17
// speedup vs baseline: 1.0954x; 1.0954x over previous
#include <cuda_runtime.h>
#include <cuda_bf16.h>
#include <cuda_fp16.h>
#include <cstdint>

#define N_NODES 100000
#define N_EDGES 1600000
#define D 128
#define SCAN_BS 512
#define NB ((N_NODES + SCAN_BS - 1) / SCAN_BS)   // 196
#define GEMM_TILE_M 64
#define GEMM_GRID ((N_NODES + GEMM_TILE_M - 1) / GEMM_TILE_M)   // 1563
#define PITCH_B 272

// ---------------- scratch ----------------------------------------------------
__device__ __half g_yh[N_NODES * D];
__device__ float g_dinv[N_NODES];
__device__ int   g_cnt[N_NODES];
__device__ int   g_rank[N_EDGES];
__device__ int   g_rowptr[N_NODES];
__device__ int   g_src[N_EDGES];
__device__ int   g_bsum[NB];
__device__ __align__(16) __nv_bfloat16 g_Ahi[N_NODES * D];
__device__ __align__(16) __nv_bfloat16 g_Alo[N_NODES * D];
__device__ __align__(16) __nv_bfloat16 g_Xhi[N_NODES * D];
__device__ __align__(16) __nv_bfloat16 g_Xlo[N_NODES * D];
__device__ __align__(16) unsigned char g_Bhi[65536];
__device__ __align__(16) unsigned char g_Blo[65536];
__device__ unsigned g_barcnt = 0;
__device__ unsigned g_bargen = 0;

__device__ __forceinline__ void grid_barrier() {
    __syncthreads();
    if (threadIdx.x == 0) {
        unsigned gen;
        asm volatile("ld.acquire.gpu.u32 %0, [%1];" : "=r"(gen) : "l"(&g_bargen));
        __threadfence();
        unsigned ticket = atomicAdd(&g_barcnt, 1);
        if (ticket == gridDim.x - 1) {
            g_barcnt = 0;
            __threadfence();
            atomicAdd(&g_bargen, 1);
        } else {
            unsigned cur;
            do {
                asm volatile("ld.acquire.gpu.u32 %0, [%1];" : "=r"(cur) : "l"(&g_bargen));
            } while (cur == gen);
        }
    }
    __syncthreads();
}

__device__ __forceinline__ void split2x2(float4 v, uint2& hp, uint2& lp) {
    __nv_bfloat16 h0 = __float2bfloat16_rn(v.x);
    __nv_bfloat16 h1 = __float2bfloat16_rn(v.y);
    __nv_bfloat16 h2 = __float2bfloat16_rn(v.z);
    __nv_bfloat16 h3 = __float2bfloat16_rn(v.w);
    __nv_bfloat16 l0 = __float2bfloat16_rn(v.x - __bfloat162float(h0));
    __nv_bfloat16 l1 = __float2bfloat16_rn(v.y - __bfloat162float(h1));
    __nv_bfloat16 l2 = __float2bfloat16_rn(v.z - __bfloat162float(h2));
    __nv_bfloat16 l3 = __float2bfloat16_rn(v.w - __bfloat162float(h3));
    hp.x = (uint32_t)__bfloat16_as_ushort(h0) | ((uint32_t)__bfloat16_as_ushort(h1) << 16);
    hp.y = (uint32_t)__bfloat16_as_ushort(h2) | ((uint32_t)__bfloat16_as_ushort(h3) << 16);
    lp.x = (uint32_t)__bfloat16_as_ushort(l0) | ((uint32_t)__bfloat16_as_ushort(l1) << 16);
    lp.y = (uint32_t)__bfloat16_as_ushort(l2) | ((uint32_t)__bfloat16_as_ushort(l3) << 16);
}

// ---------------- launch 0: zero+wconv | count | scan | prefix (1 kernel) ---
__global__ __launch_bounds__(SCAN_BS, 2)
void k_build(const int* __restrict__ col,
             const float* __restrict__ Wconv, const float* __restrict__ Wproj) {
    __shared__ int s[SCAN_BS];
    __shared__ int s2[256];
    int t = threadIdx.x;
    int bid = blockIdx.x;
    int tid0 = bid * SCAN_BS + t;

    // phase 1: zero cnt + weight split
    if (tid0 < N_NODES) g_cnt[tid0] = 0;
    if (tid0 < 128 * 128) {
        int n = tid0 >> 7;
        int p = tid0 & 127;
        int k0 = 2 * p, k1 = k0 + 1;
        float v0 = (k0 < D) ? Wconv[k0 * D + n] : Wproj[(k0 - D) * D + n];
        float v1 = (k1 < D) ? Wconv[k1 * D + n] : Wproj[(k1 - D) * D + n];
        __nv_bfloat16 h0 = __float2bfloat16_rn(v0);
        __nv_bfloat16 h1 = __float2bfloat16_rn(v1);
        __nv_bfloat16 l0 = __float2bfloat16_rn(v0 - __bfloat162float(h0));
        __nv_bfloat16 l1 = __float2bfloat16_rn(v1 - __bfloat162float(h1));
        uint32_t hp = (uint32_t)__bfloat16_as_ushort(h0) | ((uint32_t)__bfloat16_as_ushort(h1) << 16);
        uint32_t lp = (uint32_t)__bfloat16_as_ushort(l0) | ((uint32_t)__bfloat16_as_ushort(l1) << 16);
        int half = k0 >> 7;
        int klocal = k0 & 127;
        uint32_t off = ((uint32_t)half * 16384 + n * 128 + klocal) * 2;
        *(uint32_t*)(g_Bhi + off) = hp;
        *(uint32_t*)(g_Blo + off) = lp;
    }
    grid_barrier();

    // phase 2: degree count + rank
    int nthreads = gridDim.x * SCAN_BS;
    for (int e = tid0; e < N_EDGES; e += nthreads)
        g_rank[e] = atomicAdd(&g_cnt[col[e]], 1);
    grid_barrier();

    // phase 3: block-local inclusive scan + block sums
    int i = bid * SCAN_BS + t;
    int v = (i < N_NODES) ? g_cnt[i] : 0;
    s[t] = v;
    __syncthreads();
    for (int off = 1; off < SCAN_BS; off <<= 1) {
        int u = (t >= off) ? s[t - off] : 0;
        __syncthreads();
        s[t] += u;
        __syncthreads();
    }
    if (t == SCAN_BS - 1) g_bsum[bid] = s[t];
    int local_incl = s[t];
    grid_barrier();

    // phase 4: bsum prefix + rowptr/dinv
    if (t < 256) s2[t] = (t < NB) ? g_bsum[t] : 0;
    __syncthreads();
    for (int off = 1; off < 256; off <<= 1) {
        int u = 0;
        if (t < 256 && t >= off) u = s2[t - off];
        __syncthreads();
        if (t < 256) s2[t] += u;
        __syncthreads();
    }
    int bpre = (bid > 0) ? s2[bid - 1] : 0;
    if (i < N_NODES) {
        g_rowptr[i] = local_incl - v + bpre;
        g_dinv[i] = rsqrtf((float)(v + 2));
    }
}

// ---------------- launch 1: prep (yh = dinv*x fp16) + fill ------------------
#define PREP_BLOCKS 12500
__global__ void k_prepfill(const float* __restrict__ x,
                           const int* __restrict__ rowv, const int* __restrict__ colv) {
    if (blockIdx.x < PREP_BLOCKS) {
        int i = blockIdx.x * 256 + threadIdx.x;
        if (i >= N_NODES * 32) return;
        int node = i >> 5;
        float dv = g_dinv[node];
        float4 v = ((const float4*)x)[i];
        __half2 a = __floats2half2_rn(dv * v.x, dv * v.y);
        __half2 b = __floats2half2_rn(dv * v.z, dv * v.w);
        uint2 u;
        u.x = *(uint32_t*)&a;
        u.y = *(uint32_t*)&b;
        ((uint2*)g_yh)[i] = u;
    } else {
        int e = (blockIdx.x - PREP_BLOCKS) * 256 + threadIdx.x;
        if (e >= N_EDGES) return;
        int pos = g_rowptr[colv[e]] + g_rank[e];
        g_src[pos] = rowv[e];
    }
}

// ---------------- launch 2: gather agg + A/X split --------------------------
__global__ void k_agg(const float* __restrict__ x) {
    int w = (blockIdx.x * blockDim.x + threadIdx.x) >> 5;
    int lane = threadIdx.x & 31;
    if (w >= N_NODES) return;
    const uint2* yh2 = (const uint2*)g_yh;

    int start = g_rowptr[w];
    int cn = g_cnt[w];

    float ax = 0.f, ay = 0.f, az = 0.f, aw = 0.f;

    for (int base = 0; base < cn; base += 32) {
        int idx = 0;
        if (base + lane < cn) idx = g_src[start + base + lane];
        int m = min(32, cn - base);
        int j = 0;
        for (; j + 8 <= m; j += 8) {
            uint2 u[8];
#pragma unroll
            for (int q = 0; q < 8; q++) {
                int sv = __shfl_sync(0xffffffffu, idx, j + q);
                u[q] = yh2[sv * 32 + lane];
            }
            __half2 px0 = __hadd2(*(__half2*)&u[0].x, *(__half2*)&u[1].x);
            __half2 px1 = __hadd2(*(__half2*)&u[2].x, *(__half2*)&u[3].x);
            __half2 px2 = __hadd2(*(__half2*)&u[4].x, *(__half2*)&u[5].x);
            __half2 px3 = __hadd2(*(__half2*)&u[6].x, *(__half2*)&u[7].x);
            __half2 py0 = __hadd2(*(__half2*)&u[0].y, *(__half2*)&u[1].y);
            __half2 py1 = __hadd2(*(__half2*)&u[2].y, *(__half2*)&u[3].y);
            __half2 py2 = __hadd2(*(__half2*)&u[4].y, *(__half2*)&u[5].y);
            __half2 py3 = __hadd2(*(__half2*)&u[6].y, *(__half2*)&u[7].y);
            __half2 qx0 = __hadd2(px0, px1);
            __half2 qx1 = __hadd2(px2, px3);
            __half2 qy0 = __hadd2(py0, py1);
            __half2 qy1 = __hadd2(py2, py3);
            float2 fx0 = __half22float2(qx0);
            float2 fx1 = __half22float2(qx1);
            float2 fy0 = __half22float2(qy0);
            float2 fy1 = __half22float2(qy1);
            ax += fx0.x + fx1.x;
            ay += fx0.y + fx1.y;
            az += fy0.x + fy1.x;
            aw += fy0.y + fy1.y;
        }
        for (; j < m; j++) {
            int sv = __shfl_sync(0xffffffffu, idx, j);
            uint2 u0 = yh2[sv * 32 + lane];
            float2 a = __half22float2(*(__half2*)&u0.x);
            float2 b = __half22float2(*(__half2*)&u0.y);
            ax += a.x; ay += a.y; az += b.x; aw += b.y;
        }
    }

    float dc = g_dinv[w];
    float4 xv = ((const float4*)x)[w * 32 + lane];
    float td = 2.f * dc;
    float4 r;
    r.x = dc * (ax + td * xv.x);
    r.y = dc * (ay + td * xv.y);
    r.z = dc * (az + td * xv.z);
    r.w = dc * (aw + td * xv.w);

    uint2 hp, lp;
    split2x2(r, hp, lp);
    ((uint2*)g_Ahi)[w * 32 + lane] = hp;
    ((uint2*)g_Alo)[w * 32 + lane] = lp;
    split2x2(xv, hp, lp);
    ((uint2*)g_Xhi)[w * 32 + lane] = hp;
    ((uint2*)g_Xlo)[w * 32 + lane] = lp;
}

// ---------------- launch 3: TILE_M=64, 2 CTA/SM split-bf16 mma GEMM ---------
#define SM_AHI 0
#define SM_ALO 17408
#define SM_BHI 34816
#define SM_BLO 69632
#define SM_MISC 104448
#define SM_TOTAL 105984

__device__ __forceinline__ uint32_t s2u(const void* p) {
    uint32_t a;
    asm("{ .reg .u64 t; cvta.to.shared.u64 t, %1; cvt.u32.u64 %0, t; }" : "=r"(a) : "l"(p));
    return a;
}
__device__ __forceinline__ void ldsm4(uint32_t* r, uint32_t addr) {
    asm volatile("ldmatrix.sync.aligned.m8n8.x4.shared.b16 {%0,%1,%2,%3}, [%4];"
                 : "=r"(r[0]), "=r"(r[1]), "=r"(r[2]), "=r"(r[3]) : "r"(addr));
}
__device__ __forceinline__ void mma16816(float* c, const uint32_t* a, uint32_t b0, uint32_t b1) {
    asm volatile(
        "mma.sync.aligned.m16n8k16.row.col.f32.bf16.bf16.f32 "
        "{%0,%1,%2,%3}, {%4,%5,%6,%7}, {%8,%9}, {%0,%1,%2,%3};"
        : "+f"(c[0]), "+f"(c[1]), "+f"(c[2]), "+f"(c[3])
        : "r"(a[0]), "r"(a[1]), "r"(a[2]), "r"(a[3]), "r"(b0), "r"(b1));
}

__global__ __launch_bounds__(256, 2)
void k_gemm(const float* __restrict__ bconv, const float* __restrict__ bproj,
            const float* __restrict__ Wout,  const float* __restrict__ bout,
            float* __restrict__ out) {
    extern __shared__ char sm[];
    uint32_t sb = s2u(sm);
    int tid = threadIdx.x;
    int wid = tid >> 5;
    int lane = tid & 31;
    int mBase = blockIdx.x * GEMM_TILE_M;

    float* sB = (float*)(sm + SM_MISC);
    float* sO = (float*)(sm + SM_MISC + 512);
    float* sRes = (float*)(sm + SM_MISC + 1024);

    if (tid < D) {
        sB[tid] = bconv[tid] + bproj[tid];
        sO[tid] = Wout[tid];
    }
    if (tid < GEMM_TILE_M) sRes[tid] = 0.f;

    int warp_m = wid & 1;
    int warp_n = wid >> 1;

    float acc[2][4][4];
#pragma unroll
    for (int mt = 0; mt < 2; mt++)
#pragma unroll
        for (int nt = 0; nt < 4; nt++)
#pragma unroll
            for (int j = 0; j < 4; j++) acc[mt][nt][j] = 0.f;

    int l8 = lane & 7;
    int sel = lane >> 3;
    const uint4 zero4 = make_uint4(0, 0, 0, 0);

    for (int h = 0; h < 2; h++) {
        __syncthreads();

        const uint4* ahi4 = (h == 0) ? (const uint4*)g_Ahi : (const uint4*)g_Xhi;
        const uint4* alo4 = (h == 0) ? (const uint4*)g_Alo : (const uint4*)g_Xlo;
#pragma unroll
        for (int p = 0; p < 4; p++) {
            int i = p * 256 + tid;
            int r = i >> 4;
            int u = i & 15;
            int node = mBase + r;
            uint4 vh = zero4, vl = zero4;
            if (node < N_NODES) {
                vh = ahi4[node * 16 + u];
                vl = alo4[node * 16 + u];
            }
            uint32_t off = (uint32_t)r * PITCH_B + u * 16;
            *(uint4*)(sm + SM_AHI + off) = vh;
            *(uint4*)(sm + SM_ALO + off) = vl;
        }

#pragma unroll
        for (int p = 0; p < 16; p++) {
            int i = p * 256 + tid;
            int img = i >> 11;
            int j = i & 2047;
            int r = j >> 4;
            int u = j & 15;
            const unsigned char* src = (img == 0 ? g_Bhi : g_Blo) + h * 32768 + r * 256 + u * 16;
            unsigned char* dst = (unsigned char*)sm + (img == 0 ? SM_BHI : SM_BLO) + r * PITCH_B + u * 16;
            *(uint4*)dst = *(const uint4*)src;
        }
        __syncthreads();

        uint32_t aBaseHi = sb + SM_AHI + (warp_m * 32) * PITCH_B;
        uint32_t aBaseLo = sb + SM_ALO + (warp_m * 32) * PITCH_B;
        uint32_t bBaseHi = sb + SM_BHI + (warp_n * 32) * PITCH_B;
        uint32_t bBaseLo = sb + SM_BLO + (warp_n * 32) * PITCH_B;

#pragma unroll
        for (int ks = 0; ks < 8; ks++) {
            int kb = ks * 16;
            uint32_t ah[2][4], al[2][4];
#pragma unroll
            for (int mt = 0; mt < 2; mt++) {
                int row = mt * 16 + l8 + (sel & 1) * 8;
                int kk = kb + (sel >> 1) * 8;
                uint32_t o = (uint32_t)row * PITCH_B + kk * 2;
                ldsm4(ah[mt], aBaseHi + o);
                ldsm4(al[mt], aBaseLo + o);
            }
#pragma unroll
            for (int ntp = 0; ntp < 2; ntp++) {
                int row = ntp * 16 + (sel >> 1) * 8 + l8;
                int kk = kb + (sel & 1) * 8;
                uint32_t o = (uint32_t)row * PITCH_B + kk * 2;
                uint32_t bh[4], bl[4];
                ldsm4(bh, bBaseHi + o);
                ldsm4(bl, bBaseLo + o);
#pragma unroll
                for (int mt = 0; mt < 2; mt++) {
                    mma16816(acc[mt][ntp * 2],     ah[mt], bh[0], bh[1]);
                    mma16816(acc[mt][ntp * 2 + 1], ah[mt], bh[2], bh[3]);
                    mma16816(acc[mt][ntp * 2],     ah[mt], bl[0], bl[1]);
                    mma16816(acc[mt][ntp * 2 + 1], ah[mt], bl[2], bl[3]);
                    mma16816(acc[mt][ntp * 2],     al[mt], bh[0], bh[1]);
                    mma16816(acc[mt][ntp * 2 + 1], al[mt], bh[2], bh[3]);
                }
            }
        }
    }

    __syncthreads();
#pragma unroll
    for (int mt = 0; mt < 2; mt++) {
        int r0 = warp_m * 32 + mt * 16 + (lane >> 2);
        float s0 = 0.f, s1 = 0.f;
#pragma unroll
        for (int nt = 0; nt < 4; nt++) {
            int c = warp_n * 32 + nt * 8 + 2 * (lane & 3);
            s0 += fmaxf(acc[mt][nt][0] + sB[c], 0.f) * sO[c];
            s0 += fmaxf(acc[mt][nt][1] + sB[c + 1], 0.f) * sO[c + 1];
            s1 += fmaxf(acc[mt][nt][2] + sB[c], 0.f) * sO[c];
            s1 += fmaxf(acc[mt][nt][3] + sB[c + 1], 0.f) * sO[c + 1];
        }
        atomicAdd(&sRes[r0], s0);
        atomicAdd(&sRes[r0 + 8], s1);
    }
    __syncthreads();
    if (tid < GEMM_TILE_M) {
        int node = mBase + tid;
        if (node < N_NODES) out[node] = sRes[tid] + bout[0];
    }
}

// ---------------- launch -----------------------------------------------------
extern "C" void kernel_launch(void* const* d_in, const int* in_sizes, int n_in,
                              void* d_out, int out_size) {
    const float* x      = (const float*)d_in[0];
    const int*   ei     = (const int*)d_in[1];
    const float* Wconv  = (const float*)d_in[2];
    const float* bconv  = (const float*)d_in[3];
    const float* Wproj  = (const float*)d_in[4];
    const float* bproj  = (const float*)d_in[5];
    const float* Wout   = (const float*)d_in[6];
    const float* bout   = (const float*)d_in[7];
    float* out = (float*)d_out;

    const int* rowv = ei;
    const int* colv = ei + N_EDGES;

    k_build<<<NB, SCAN_BS>>>(colv, Wconv, Wproj);              // 0 (zero+wconv+count+scan)
    k_prepfill<<<PREP_BLOCKS + (N_EDGES + 255) / 256, 256>>>(x, rowv, colv);  // 1
    long long agg_threads = (long long)N_NODES * 32;
    k_agg<<<(unsigned)((agg_threads + 255) / 256), 256>>>(x);   // 2
    static bool attr_set = false;
    if (!attr_set) {
        cudaFuncSetAttribute(k_gemm, cudaFuncAttributeMaxDynamicSharedMemorySize, SM_TOTAL);
        attr_set = true;
    }
    k_gemm<<<GEMM_GRID, 256, SM_TOTAL>>>(bconv, bproj, Wout, bout, out);      // 3
}